// round 14
// baseline (speedup 1.0000x reference)
#include <cuda_runtime.h>
#include <cuda_fp16.h>
#include <math.h>

#define S_LEN   4096
#define D_MODEL 768
#define NH      12
#define DHEAD   64
#define BATCH   2
#define ROWS    (BATCH * S_LEN)   // 8192
#define QS      (3 * D_MODEL)     // fused QKV row stride = 2304

// exp2-domain scale: 0.125 * log2(e)
#define CEXP 0.180336880f
// half2 {1.0, 1.0}
#define ONES2 0x3C003C00u

// fp16 scratch (allocation-free rule: __device__ globals)
__device__ __half g_h16[ROWS * D_MODEL];
__device__ __half g_wqkv[3 * D_MODEL * D_MODEL];   // rows: Wq | Wk | Wv
__device__ float  g_bqkv[QS];
__device__ __half g_wo[D_MODEL * D_MODEL];
__device__ __half g_qkv[ROWS * QS];                // [row][2304] = Q|K|V
__device__ __half g_att[ROWS * D_MODEL];

// ---------------------------------------------------------------------------
// helpers
// ---------------------------------------------------------------------------
__device__ __forceinline__ unsigned pack2(float a, float b) {
    __half2 h = __floats2half2_rn(a, b);
    return *(unsigned*)&h;
}

__device__ __forceinline__ unsigned h2ex2(unsigned x) {
    unsigned y;
    asm("ex2.approx.f16x2 %0, %1;" : "=r"(y) : "r"(x));
    return y;
}

__device__ __forceinline__ void mma_f16(float c[4], const unsigned a[4],
                                        unsigned b0, unsigned b1) {
    asm volatile(
        "mma.sync.aligned.m16n8k16.row.col.f32.f16.f16.f32 "
        "{%0,%1,%2,%3}, {%4,%5,%6,%7}, {%8,%9}, {%0,%1,%2,%3};"
        : "+f"(c[0]), "+f"(c[1]), "+f"(c[2]), "+f"(c[3])
        : "r"(a[0]), "r"(a[1]), "r"(a[2]), "r"(a[3]), "r"(b0), "r"(b1));
}

__device__ __forceinline__ void ldsm4(unsigned r[4], const __half* p) {
    unsigned addr = (unsigned)__cvta_generic_to_shared(p);
    asm volatile("ldmatrix.sync.aligned.m8n8.x4.shared.b16 {%0,%1,%2,%3}, [%4];"
                 : "=r"(r[0]), "=r"(r[1]), "=r"(r[2]), "=r"(r[3]) : "r"(addr));
}

__device__ __forceinline__ void ldsm4t(unsigned r[4], const __half* p) {
    unsigned addr = (unsigned)__cvta_generic_to_shared(p);
    asm volatile("ldmatrix.sync.aligned.m8n8.x4.trans.shared.b16 {%0,%1,%2,%3}, [%4];"
                 : "=r"(r[0]), "=r"(r[1]), "=r"(r[2]), "=r"(r[3]) : "r"(addr));
}

__device__ __forceinline__ void cpa16(void* dst, const void* src) {
    unsigned d = (unsigned)__cvta_generic_to_shared(dst);
    asm volatile("cp.async.cg.shared.global [%0], [%1], 16;" :: "r"(d), "l"(src));
}
__device__ __forceinline__ void cpa_commit() {
    asm volatile("cp.async.commit_group;");
}
__device__ __forceinline__ void cpa_wait1() {
    asm volatile("cp.async.wait_group 1;");
}
__device__ __forceinline__ void cpa_wait0() {
    asm volatile("cp.async.wait_group 0;");
}

// ---------------------------------------------------------------------------
// single fused fp32->fp16 conversion kernel (h, Wq|Wk|Wv, Wo, bias concat)
// ---------------------------------------------------------------------------
#define NH4 (ROWS * D_MODEL / 4)        // 1572864
#define NW4 (D_MODEL * D_MODEL / 4)     // 147456
#define NB4 (D_MODEL / 4)               // 192

__global__ void cvt_all(const float* __restrict__ h,
                        const float* __restrict__ Wq, const float* __restrict__ Wk,
                        const float* __restrict__ Wv, const float* __restrict__ Wo,
                        const float* __restrict__ bq, const float* __restrict__ bk,
                        const float* __restrict__ bv,
                        __half* __restrict__ h16, __half* __restrict__ wqkv,
                        __half* __restrict__ wo, float* __restrict__ bqkv)
{
    int i = blockIdx.x * blockDim.x + threadIdx.x;
    const float* src;
    __half* dst;
    int j;
    if (i < NH4) { src = h; dst = h16; j = i; }
    else if (i < NH4 + NW4)     { src = Wq; dst = wqkv;                           j = i - NH4; }
    else if (i < NH4 + 2 * NW4) { src = Wk; dst = wqkv + D_MODEL * D_MODEL;       j = i - NH4 - NW4; }
    else if (i < NH4 + 3 * NW4) { src = Wv; dst = wqkv + 2 * D_MODEL * D_MODEL;   j = i - NH4 - 2 * NW4; }
    else if (i < NH4 + 4 * NW4) { src = Wo; dst = wo;                             j = i - NH4 - 3 * NW4; }
    else {
        j = i - NH4 - 4 * NW4;
        if (j < 3 * NB4) {
            const float* bsrc = (j < NB4) ? bq : (j < 2 * NB4) ? bk : bv;
            int k = (j < NB4) ? j : (j < 2 * NB4) ? j - NB4 : j - 2 * NB4;
            ((float4*)bqkv)[j] = ((const float4*)bsrc)[k];
        }
        return;
    }
    float4 v = ((const float4*)src)[j];
    ((uint2*)dst)[j] = make_uint2(pack2(v.x, v.y), pack2(v.z, v.w));
}

// ---------------------------------------------------------------------------
// C[M,N] = A[M,K] @ W[N,K]^T + bias   (all-fp16 inputs, fp32 accum)
// Block 128x128, BK=32, 512 threads (16 warps, 4x4), warp tile 32x32.
// 2 CTAs/SM = 32 warps. 3-stage cp.async ring, ONE __syncthreads per k-tile.
// ---------------------------------------------------------------------------
#define GH 40
#define GSTG (128 * GH)    // halves per stage per matrix

template<bool HALF_OUT>
__global__ void __launch_bounds__(512, 2) gemm_h(
    const __half* __restrict__ A, const __half* __restrict__ W,
    const float* __restrict__ bias, void* __restrict__ Cv,
    int M, int N, int K)
{
    extern __shared__ __half gsm[];
    __half* As = gsm;               // 3 x 128*40
    __half* Bs = gsm + 3 * GSTG;    // 3 x 128*40

    const int t    = threadIdx.x;
    const int warp = t >> 5;
    const int lane = t & 31;
    const int g    = lane >> 2;
    const int tig  = lane & 3;
    const int q8   = lane >> 3;
    const int ri   = lane & 7;
    const int wm   = warp >> 2;       // 0..3 (row tile, 32 rows)
    const int wn   = warp & 3;        // 0..3 (col tile, 32 cols)
    const int m0   = blockIdx.y * 128;
    const int n0   = blockIdx.x * 128;

    const int lrow = t >> 2;          // 0..127
    const int lc   = t & 3;           // chunk 0..3

    float acc[2][4][4] = {};

    // prologue: stages 0 and 1
#pragma unroll
    for (int st = 0; st < 2; st++) {
        const int k0 = st * 32;
        cpa16(&As[st * GSTG + lrow * GH + lc * 8],
              A + (size_t)(m0 + lrow) * K + k0 + lc * 8);
        cpa16(&Bs[st * GSTG + lrow * GH + lc * 8],
              W + (size_t)(n0 + lrow) * K + k0 + lc * 8);
        cpa_commit();
    }

    const int nk = K / 32;
    for (int it = 0; it < nk; it++) {
        const int stage = it % 3;
        if (it + 1 < nk) cpa_wait1(); else cpa_wait0();
        __syncthreads();   // stage data visible; all warps done with it-1

        if (it + 2 < nk) {
            const int k0 = (it + 2) * 32;
            const int sbuf = (it + 2) % 3;
            cpa16(&As[sbuf * GSTG + lrow * GH + lc * 8],
                  A + (size_t)(m0 + lrow) * K + k0 + lc * 8);
            cpa16(&Bs[sbuf * GSTG + lrow * GH + lc * 8],
                  W + (size_t)(n0 + lrow) * K + k0 + lc * 8);
            cpa_commit();
        }

        const __half* Ab = As + stage * GSTG;
        const __half* Bb = Bs + stage * GSTG;

#pragma unroll
        for (int ks = 0; ks < 2; ks++) {
            unsigned a[2][4];
#pragma unroll
            for (int ti = 0; ti < 2; ti++)
                ldsm4(a[ti], &Ab[(wm * 32 + ti * 16 + (q8 & 1) * 8 + ri) * GH
                                 + ks * 16 + (q8 >> 1) * 8]);
#pragma unroll
            for (int nt = 0; nt < 4; nt += 2) {
                unsigned b[4];
                ldsm4(b, &Bb[(wn * 32 + (nt + (q8 >> 1)) * 8 + ri) * GH
                             + ks * 16 + (q8 & 1) * 8]);
                mma_f16(acc[0][nt],     a[0], b[0], b[1]);
                mma_f16(acc[1][nt],     a[1], b[0], b[1]);
                mma_f16(acc[0][nt + 1], a[0], b[2], b[3]);
                mma_f16(acc[1][nt + 1], a[1], b[2], b[3]);
            }
        }
    }

#pragma unroll
    for (int ti = 0; ti < 2; ti++) {
        const int row0 = m0 + wm * 32 + ti * 16 + g;
#pragma unroll
        for (int nt = 0; nt < 4; nt++) {
            const int col = n0 + wn * 32 + nt * 8 + 2 * tig;
            const float b0v = bias[col], b1v = bias[col + 1];
            if (HALF_OUT) {
                __half* C = (__half*)Cv;
                *(unsigned*)&C[(size_t)row0 * N + col] =
                    pack2(acc[ti][nt][0] + b0v, acc[ti][nt][1] + b1v);
                *(unsigned*)&C[(size_t)(row0 + 8) * N + col] =
                    pack2(acc[ti][nt][2] + b0v, acc[ti][nt][3] + b1v);
            } else {
                float* C = (float*)Cv;
                *(float2*)&C[(size_t)row0 * N + col] =
                    make_float2(acc[ti][nt][0] + b0v, acc[ti][nt][1] + b1v);
                *(float2*)&C[(size_t)(row0 + 8) * N + col] =
                    make_float2(acc[ti][nt][2] + b0v, acc[ti][nt][3] + b1v);
            }
        }
    }
}

#define GEMM_SMEM (6 * GSTG * 2)   // 61440 bytes

// ---------------------------------------------------------------------------
// Flash attention: 256 threads / 8 warps, 16 q-rows per warp (q-tile 128),
// KTILE=128 keys per mainloop iteration (two 64-key halves), 2-stage ring,
// prefetch distance 1 (covered by a full 128-key compute), ONE barrier/iter.
// A operands (Q, P) register-resident; 2 CTAs/SM. fp16 MMA, no-max softmax
// (ex2.approx.f16x2), l via ones-MMA.
// smem: Qh[128*72] | Kh[2][128*72] | Vh[2][128*72] | biasf[4096]  = 106 KB
// ---------------------------------------------------------------------------
#define HST 72
#define KTILE 128
#define KSTG (KTILE * HST)

__global__ void __launch_bounds__(256, 2) attn_tc(
    const __half* __restrict__ qkv, const int* __restrict__ mask,
    __half* __restrict__ Og)
{
    extern __shared__ __half sh[];
    __half* Qh = sh;                         // 128*72
    __half* Kh = Qh + 128 * HST;             // 2 x 128*72
    __half* Vh = Kh + 2 * KSTG;              // 2 x 128*72
    float* biasf = (float*)(Vh + 2 * KSTG);  // 4096 floats

    const int t    = threadIdx.x;
    const int warp = t >> 5;
    const int lane = t & 31;
    const int tig  = lane & 3;
    const int q8   = lane >> 3;
    const int ri   = lane & 7;

    const int qb = blockIdx.x;
    const int bh = blockIdx.y;
    const int b  = bh / NH;
    const int hh = bh % NH;
    const int qrow0 = b * S_LEN + qb * 128;
    const int hcol  = hh * DHEAD;

    const int R0 = warp * 16;
    const int kvrow = t >> 1;        // 0..127
    const int kvcb  = (t & 1) * 4;   // 4 chunks of 8 halves each

    const __half* Kg = qkv + D_MODEL + hcol;
    const __half* Vg = qkv + 2 * D_MODEL + hcol;

    // prologue: G0 = Q tile + KV stage 0; mask via LDG (overlapped)
    {
        const int qrow = t >> 1;         // 0..127
        const int qcb  = (t & 1) * 4;    // 4 chunks
#pragma unroll
        for (int c = 0; c < 4; c++)
            cpa16(&Qh[qrow * HST + (qcb + c) * 8],
                  qkv + (size_t)(qrow0 + qrow) * QS + hcol + (qcb + c) * 8);
        const size_t krow0 = (size_t)b * S_LEN + kvrow;
#pragma unroll
        for (int c = 0; c < 4; c++) {
            cpa16(&Kh[kvrow * HST + (kvcb + c) * 8], Kg + krow0 * QS + (kvcb + c) * 8);
            cpa16(&Vh[kvrow * HST + (kvcb + c) * 8], Vg + krow0 * QS + (kvcb + c) * 8);
        }
        cpa_commit();

        // mask: 4096 ints -> bias floats (0 or -1e30)
#pragma unroll
        for (int i = 0; i < 4; i++) {
            const int idx = t + 256 * i;   // int4 chunk id, 1024 total
            int4 m4 = ((const int4*)(mask + (size_t)b * S_LEN))[idx];
            float4 f4;
            f4.x = m4.x ? -1e30f : 0.f;
            f4.y = m4.y ? -1e30f : 0.f;
            f4.z = m4.z ? -1e30f : 0.f;
            f4.w = m4.w ? -1e30f : 0.f;
            ((float4*)biasf)[idx] = f4;
        }
    }

    unsigned qa[4][4];       // Q fragments (one m16 tile), loaded once at jb==0
    float o[8][4] = {};
    float ol[4] = {};        // l via ones-MMA (c0 = row g, c2 = row g+8)

    const int NT = S_LEN / KTILE;   // 32
    for (int jb = 0; jb < NT; jb++) {
        const int buf = jb & 1;
        cpa_wait0();       // group issued one full 128-key compute ago
        __syncthreads();   // copies visible; all warps done with iter jb-1

        if (jb == 0) {
#pragma unroll
            for (int kc = 0; kc < 4; kc++)
                ldsm4(qa[kc], &Qh[(R0 + (q8 & 1) * 8 + ri) * HST
                                  + kc * 16 + (q8 >> 1) * 8]);
        }

        // prefetch stage jb+1 into buf^1 (read at jb-1 -> safe now)
        if (jb + 1 < NT) {
            const size_t krow = (size_t)b * S_LEN + (jb + 1) * KTILE + kvrow;
            const int sb = (buf ^ 1) * KSTG;
#pragma unroll
            for (int c = 0; c < 4; c++) {
                cpa16(&Kh[sb + kvrow * HST + (kvcb + c) * 8],
                      Kg + krow * QS + (kvcb + c) * 8);
                cpa16(&Vh[sb + kvrow * HST + (kvcb + c) * 8],
                      Vg + krow * QS + (kvcb + c) * 8);
            }
            cpa_commit();
        }

        // ---- two 64-key halves ----
#pragma unroll
        for (int h2 = 0; h2 < 2; h2++) {
            const __half* Kb = Kh + buf * KSTG + h2 * 64 * HST;
            const __half* Vb = Vh + buf * KSTG + h2 * 64 * HST;
            const float* brow = biasf + jb * KTILE + h2 * 64;

            // S = Q @ K^T (Q from registers)
            float s[8][4] = {};
#pragma unroll
            for (int kc = 0; kc < 4; kc++) {
#pragma unroll
                for (int nt = 0; nt < 8; nt += 2) {
                    unsigned bb[4];
                    ldsm4(bb, &Kb[((nt + (q8 >> 1)) * 8 + ri) * HST + kc * 16 + (q8 & 1) * 8]);
                    mma_f16(s[nt],     qa[kc], bb[0], bb[1]);
                    mma_f16(s[nt + 1], qa[kc], bb[2], bb[3]);
                }
            }

            // p = ex2.f16x2(half2(s*CEXP + bias)) straight into PV A-frags
            unsigned pa[4][4];
#pragma unroll
            for (int nt = 0; nt < 8; nt++) {
                const float2 bj = *(const float2*)&brow[nt * 8 + 2 * tig];
                unsigned x01 = pack2(fmaf(s[nt][0], CEXP, bj.x),
                                     fmaf(s[nt][1], CEXP, bj.y));
                unsigned x23 = pack2(fmaf(s[nt][2], CEXP, bj.x),
                                     fmaf(s[nt][3], CEXP, bj.y));
                pa[nt >> 1][(nt & 1) * 2 + 0] = h2ex2(x01);
                pa[nt >> 1][(nt & 1) * 2 + 1] = h2ex2(x23);
            }

            // O += P @ V (V via ldmatrix.trans); l += P @ ones
#pragma unroll
            for (int kc = 0; kc < 4; kc++) {
#pragma unroll
                for (int nt = 0; nt < 8; nt += 2) {
                    unsigned bb[4];
                    ldsm4t(bb, &Vb[(kc * 16 + (q8 & 1) * 8 + ri) * HST + (nt + (q8 >> 1)) * 8]);
                    mma_f16(o[nt],     pa[kc], bb[0], bb[1]);
                    mma_f16(o[nt + 1], pa[kc], bb[2], bb[3]);
                }
                mma_f16(ol, pa[kc], ONES2, ONES2);
            }
        }
    }

    // ---- normalize + write (half out); ol[0] = l(row g), ol[2] = l(row g+8)
    {
        const float inv0 = 1.f / ol[0];
        const float inv1 = 1.f / ol[2];
        const int row0 = qrow0 + R0 + (lane >> 2);
#pragma unroll
        for (int nt = 0; nt < 8; nt++) {
            const int col = hcol + nt * 8 + 2 * tig;
            *(unsigned*)&Og[(size_t)row0 * D_MODEL + col] =
                pack2(o[nt][0] * inv0, o[nt][1] * inv0);
            *(unsigned*)&Og[(size_t)(row0 + 8) * D_MODEL + col] =
                pack2(o[nt][2] * inv1, o[nt][3] * inv1);
        }
    }
}

#define ATTN_SMEM ((128 * HST + 2 * KSTG + 2 * KSTG) * 2 + S_LEN * 4)  // 108544

// ---------------------------------------------------------------------------
extern "C" void kernel_launch(void* const* d_in, const int* in_sizes, int n_in,
                              void* d_out, int out_size)
{
    const float* h   = (const float*)d_in[0];
    const float* Wq  = (const float*)d_in[1];
    const float* bq  = (const float*)d_in[2];
    const float* Wk  = (const float*)d_in[3];
    const float* bk  = (const float*)d_in[4];
    const float* Wv  = (const float*)d_in[5];
    const float* bv  = (const float*)d_in[6];
    const float* Wo  = (const float*)d_in[7];
    const float* bo  = (const float*)d_in[8];
    const int*   msk = (const int*)d_in[9];
    float* out = (float*)d_out;

    void *ph16, *pwqkv, *pbqkv, *pwo, *pqkv, *pa;
    cudaGetSymbolAddress(&ph16, g_h16);
    cudaGetSymbolAddress(&pwqkv, g_wqkv);
    cudaGetSymbolAddress(&pbqkv, g_bqkv);
    cudaGetSymbolAddress(&pwo, g_wo);
    cudaGetSymbolAddress(&pqkv, g_qkv);
    cudaGetSymbolAddress(&pa, g_att);

    // single fused fp32 -> fp16 pre-conversion
    {
        const int total = NH4 + 4 * NW4 + 3 * NB4;
        cvt_all<<<(total + 255) / 256, 256>>>(h, Wq, Wk, Wv, Wo, bq, bk, bv,
                                              (__half*)ph16, (__half*)pwqkv,
                                              (__half*)pwo, (float*)pbqkv);
    }

    cudaFuncSetAttribute(attn_tc, cudaFuncAttributeMaxDynamicSharedMemorySize,
                         ATTN_SMEM);
    cudaFuncSetAttribute(gemm_h<true>, cudaFuncAttributeMaxDynamicSharedMemorySize,
                         GEMM_SMEM);
    cudaFuncSetAttribute(gemm_h<false>, cudaFuncAttributeMaxDynamicSharedMemorySize,
                         GEMM_SMEM);

    // fused QKV projection: [8192 x 2304] = h @ [Wq|Wk|Wv]^T + b
    dim3 qgrid(QS / 128, ROWS / 128);       // (18, 64)
    gemm_h<true><<<qgrid, dim3(512), GEMM_SMEM>>>(
        (const __half*)ph16, (const __half*)pwqkv,
        (const float*)pbqkv, pqkv, ROWS, QS, D_MODEL);

    dim3 agrid(S_LEN / 128, BATCH * NH);    // (32, 24)
    attn_tc<<<agrid, dim3(256), ATTN_SMEM>>>((const __half*)pqkv, msk, (__half*)pa);

    dim3 ogrid(D_MODEL / 128, ROWS / 128);  // (6, 64)
    gemm_h<false><<<ogrid, dim3(512), GEMM_SMEM>>>(
        (const __half*)pa, (const __half*)pwo, bo, out,
        ROWS, D_MODEL, D_MODEL);
}

// round 16
// speedup vs baseline: 1.1312x; 1.1312x over previous
#include <cuda_runtime.h>
#include <cuda_fp16.h>
#include <math.h>

#define S_LEN   4096
#define D_MODEL 768
#define NH      12
#define DHEAD   64
#define BATCH   2
#define ROWS    (BATCH * S_LEN)   // 8192
#define QS      (3 * D_MODEL)     // fused QKV row stride = 2304

// exp2-domain scale: 0.125 * log2(e)
#define CEXP 0.180336880f
// half2 {1.0, 1.0}
#define ONES2 0x3C003C00u

// fp16 scratch (allocation-free rule: __device__ globals)
__device__ __half g_h16[ROWS * D_MODEL];
__device__ __half g_wqkv[3 * D_MODEL * D_MODEL];   // rows: Wq | Wk | Wv
__device__ float  g_bqkv[QS];
__device__ __half g_wo[D_MODEL * D_MODEL];
__device__ __half g_qkv[ROWS * QS];                // [row][2304] = Q|K|V
__device__ __half g_att[ROWS * D_MODEL];

// ---------------------------------------------------------------------------
// helpers
// ---------------------------------------------------------------------------
__device__ __forceinline__ unsigned pack2(float a, float b) {
    __half2 h = __floats2half2_rn(a, b);
    return *(unsigned*)&h;
}

__device__ __forceinline__ unsigned h2ex2(unsigned x) {
    unsigned y;
    asm("ex2.approx.f16x2 %0, %1;" : "=r"(y) : "r"(x));
    return y;
}

__device__ __forceinline__ void mma_f16(float c[4], const unsigned a[4],
                                        unsigned b0, unsigned b1) {
    asm volatile(
        "mma.sync.aligned.m16n8k16.row.col.f32.f16.f16.f32 "
        "{%0,%1,%2,%3}, {%4,%5,%6,%7}, {%8,%9}, {%0,%1,%2,%3};"
        : "+f"(c[0]), "+f"(c[1]), "+f"(c[2]), "+f"(c[3])
        : "r"(a[0]), "r"(a[1]), "r"(a[2]), "r"(a[3]), "r"(b0), "r"(b1));
}

__device__ __forceinline__ void ldsm4(unsigned r[4], const __half* p) {
    unsigned addr = (unsigned)__cvta_generic_to_shared(p);
    asm volatile("ldmatrix.sync.aligned.m8n8.x4.shared.b16 {%0,%1,%2,%3}, [%4];"
                 : "=r"(r[0]), "=r"(r[1]), "=r"(r[2]), "=r"(r[3]) : "r"(addr));
}

__device__ __forceinline__ void ldsm4t(unsigned r[4], const __half* p) {
    unsigned addr = (unsigned)__cvta_generic_to_shared(p);
    asm volatile("ldmatrix.sync.aligned.m8n8.x4.trans.shared.b16 {%0,%1,%2,%3}, [%4];"
                 : "=r"(r[0]), "=r"(r[1]), "=r"(r[2]), "=r"(r[3]) : "r"(addr));
}

__device__ __forceinline__ void cpa16(void* dst, const void* src) {
    unsigned d = (unsigned)__cvta_generic_to_shared(dst);
    asm volatile("cp.async.cg.shared.global [%0], [%1], 16;" :: "r"(d), "l"(src));
}
__device__ __forceinline__ void cpa_commit() {
    asm volatile("cp.async.commit_group;");
}
__device__ __forceinline__ void cpa_wait1() {
    asm volatile("cp.async.wait_group 1;");
}
__device__ __forceinline__ void cpa_wait0() {
    asm volatile("cp.async.wait_group 0;");
}

// ---------------------------------------------------------------------------
// single fused fp32->fp16 conversion kernel (h, Wq|Wk|Wv, Wo, bias concat)
// ---------------------------------------------------------------------------
#define NH4 (ROWS * D_MODEL / 4)        // 1572864
#define NW4 (D_MODEL * D_MODEL / 4)     // 147456
#define NB4 (D_MODEL / 4)               // 192

__global__ void cvt_all(const float* __restrict__ h,
                        const float* __restrict__ Wq, const float* __restrict__ Wk,
                        const float* __restrict__ Wv, const float* __restrict__ Wo,
                        const float* __restrict__ bq, const float* __restrict__ bk,
                        const float* __restrict__ bv,
                        __half* __restrict__ h16, __half* __restrict__ wqkv,
                        __half* __restrict__ wo, float* __restrict__ bqkv)
{
    int i = blockIdx.x * blockDim.x + threadIdx.x;
    const float* src;
    __half* dst;
    int j;
    if (i < NH4) { src = h; dst = h16; j = i; }
    else if (i < NH4 + NW4)     { src = Wq; dst = wqkv;                           j = i - NH4; }
    else if (i < NH4 + 2 * NW4) { src = Wk; dst = wqkv + D_MODEL * D_MODEL;       j = i - NH4 - NW4; }
    else if (i < NH4 + 3 * NW4) { src = Wv; dst = wqkv + 2 * D_MODEL * D_MODEL;   j = i - NH4 - 2 * NW4; }
    else if (i < NH4 + 4 * NW4) { src = Wo; dst = wo;                             j = i - NH4 - 3 * NW4; }
    else {
        j = i - NH4 - 4 * NW4;
        if (j < 3 * NB4) {
            const float* bsrc = (j < NB4) ? bq : (j < 2 * NB4) ? bk : bv;
            int k = (j < NB4) ? j : (j < 2 * NB4) ? j - NB4 : j - 2 * NB4;
            ((float4*)bqkv)[j] = ((const float4*)bsrc)[k];
        }
        return;
    }
    float4 v = ((const float4*)src)[j];
    ((uint2*)dst)[j] = make_uint2(pack2(v.x, v.y), pack2(v.z, v.w));
}

// ---------------------------------------------------------------------------
// C[M,N] = A[M,K] @ W[N,K]^T + bias   (all-fp16 inputs, fp32 accum)
// Block 128x128, BK=32, 512 threads (16 warps, 4x4), warp tile 32x32.
// 2 CTAs/SM = 32 warps. 3-stage cp.async ring, ONE __syncthreads per k-tile.
// #pragma unroll 3 folds stage = it%3 to compile-time constants.
// ---------------------------------------------------------------------------
#define GH 40
#define GSTG (128 * GH)    // halves per stage per matrix

template<bool HALF_OUT>
__global__ void __launch_bounds__(512, 2) gemm_h(
    const __half* __restrict__ A, const __half* __restrict__ W,
    const float* __restrict__ bias, void* __restrict__ Cv,
    int M, int N, int K)
{
    extern __shared__ __half gsm[];
    __half* As = gsm;               // 3 x 128*40
    __half* Bs = gsm + 3 * GSTG;    // 3 x 128*40

    const int t    = threadIdx.x;
    const int warp = t >> 5;
    const int lane = t & 31;
    const int g    = lane >> 2;
    const int tig  = lane & 3;
    const int q8   = lane >> 3;
    const int ri   = lane & 7;
    const int wm   = warp >> 2;       // 0..3 (row tile, 32 rows)
    const int wn   = warp & 3;        // 0..3 (col tile, 32 cols)
    const int m0   = blockIdx.y * 128;
    const int n0   = blockIdx.x * 128;

    const int lrow = t >> 2;          // 0..127
    const int lc   = t & 3;           // chunk 0..3

    float acc[2][4][4] = {};

    // prologue: stages 0 and 1
#pragma unroll
    for (int st = 0; st < 2; st++) {
        const int k0 = st * 32;
        cpa16(&As[st * GSTG + lrow * GH + lc * 8],
              A + (size_t)(m0 + lrow) * K + k0 + lc * 8);
        cpa16(&Bs[st * GSTG + lrow * GH + lc * 8],
              W + (size_t)(n0 + lrow) * K + k0 + lc * 8);
        cpa_commit();
    }

    const int nk = K / 32;   // 24 for all our shapes: divisible by 3
#pragma unroll 3
    for (int it = 0; it < nk; it++) {
        const int stage = it % 3;
        if (it + 1 < nk) cpa_wait1(); else cpa_wait0();
        __syncthreads();   // stage data visible; all warps done with it-1

        if (it + 2 < nk) {
            const int k0 = (it + 2) * 32;
            const int sbuf = (it + 2) % 3;
            cpa16(&As[sbuf * GSTG + lrow * GH + lc * 8],
                  A + (size_t)(m0 + lrow) * K + k0 + lc * 8);
            cpa16(&Bs[sbuf * GSTG + lrow * GH + lc * 8],
                  W + (size_t)(n0 + lrow) * K + k0 + lc * 8);
            cpa_commit();
        }

        const __half* Ab = As + stage * GSTG;
        const __half* Bb = Bs + stage * GSTG;

#pragma unroll
        for (int ks = 0; ks < 2; ks++) {
            unsigned a[2][4];
#pragma unroll
            for (int ti = 0; ti < 2; ti++)
                ldsm4(a[ti], &Ab[(wm * 32 + ti * 16 + (q8 & 1) * 8 + ri) * GH
                                 + ks * 16 + (q8 >> 1) * 8]);
#pragma unroll
            for (int nt = 0; nt < 4; nt += 2) {
                unsigned b[4];
                ldsm4(b, &Bb[(wn * 32 + (nt + (q8 >> 1)) * 8 + ri) * GH
                             + ks * 16 + (q8 & 1) * 8]);
                mma_f16(acc[0][nt],     a[0], b[0], b[1]);
                mma_f16(acc[1][nt],     a[1], b[0], b[1]);
                mma_f16(acc[0][nt + 1], a[0], b[2], b[3]);
                mma_f16(acc[1][nt + 1], a[1], b[2], b[3]);
            }
        }
    }

#pragma unroll
    for (int ti = 0; ti < 2; ti++) {
        const int row0 = m0 + wm * 32 + ti * 16 + g;
#pragma unroll
        for (int nt = 0; nt < 4; nt++) {
            const int col = n0 + wn * 32 + nt * 8 + 2 * tig;
            const float b0v = bias[col], b1v = bias[col + 1];
            if (HALF_OUT) {
                __half* C = (__half*)Cv;
                *(unsigned*)&C[(size_t)row0 * N + col] =
                    pack2(acc[ti][nt][0] + b0v, acc[ti][nt][1] + b1v);
                *(unsigned*)&C[(size_t)(row0 + 8) * N + col] =
                    pack2(acc[ti][nt][2] + b0v, acc[ti][nt][3] + b1v);
            } else {
                float* C = (float*)Cv;
                *(float2*)&C[(size_t)row0 * N + col] =
                    make_float2(acc[ti][nt][0] + b0v, acc[ti][nt][1] + b1v);
                *(float2*)&C[(size_t)(row0 + 8) * N + col] =
                    make_float2(acc[ti][nt][2] + b0v, acc[ti][nt][3] + b1v);
            }
        }
    }
}

#define GEMM_SMEM (6 * GSTG * 2)   // 61440 bytes

// ---------------------------------------------------------------------------
// Flash attention (R13 structure): 256 threads / 8 warps, 16 q-rows per warp,
// 64-key iterations, 3-stage cp.async ring, ONE __syncthreads per iter,
// Q/P register-resident, no-max softmax (ex2.approx.f16x2), l via ones-MMA.
// #pragma unroll 3 folds stage = jb%3 to compile-time constants.
// smem: Qh[128*72] | Kh[3][64*72] | Vh[3][64*72] | biasf[4096]
// ---------------------------------------------------------------------------
#define HST 72

__global__ void __launch_bounds__(256, 2) attn_tc(
    const __half* __restrict__ qkv, const int* __restrict__ mask,
    __half* __restrict__ Og)
{
    extern __shared__ __half sh[];
    __half* Qh = sh;                         // 128*72
    __half* Kh = Qh + 128 * HST;             // 3 x 64*72
    __half* Vh = Kh + 3 * 64 * HST;          // 3 x 64*72
    float* biasf = (float*)(Vh + 3 * 64 * HST); // 4096 floats

    const int t    = threadIdx.x;
    const int warp = t >> 5;
    const int lane = t & 31;
    const int tig  = lane & 3;
    const int q8   = lane >> 3;
    const int ri   = lane & 7;

    const int qb = blockIdx.x;
    const int bh = blockIdx.y;
    const int b  = bh / NH;
    const int hh = bh % NH;
    const int qrow0 = b * S_LEN + qb * 128;
    const int hcol  = hh * DHEAD;

    const int R0 = warp * 16;
    const int kvrow = t >> 2;        // 0..63
    const int kvcb  = (t & 3) * 2;   // 2 chunks of 8 halves each

    const __half* Kg = qkv + D_MODEL + hcol;
    const __half* Vg = qkv + 2 * D_MODEL + hcol;

    // prologue: G0 = Q tile + KV stage 0; G1 = KV stage 1; mask via LDG
    {
        const int qrow = t >> 1;         // 0..127
        const int qcb  = (t & 1) * 4;    // 4 chunks
#pragma unroll
        for (int c = 0; c < 4; c++)
            cpa16(&Qh[qrow * HST + (qcb + c) * 8],
                  qkv + (size_t)(qrow0 + qrow) * QS + hcol + (qcb + c) * 8);
        const size_t krow0 = (size_t)b * S_LEN + kvrow;
#pragma unroll
        for (int c = 0; c < 2; c++) {
            cpa16(&Kh[kvrow * HST + (kvcb + c) * 8], Kg + krow0 * QS + (kvcb + c) * 8);
            cpa16(&Vh[kvrow * HST + (kvcb + c) * 8], Vg + krow0 * QS + (kvcb + c) * 8);
        }
        cpa_commit();
#pragma unroll
        for (int c = 0; c < 2; c++) {
            cpa16(&Kh[64 * HST + kvrow * HST + (kvcb + c) * 8],
                  Kg + (krow0 + 64) * QS + (kvcb + c) * 8);
            cpa16(&Vh[64 * HST + kvrow * HST + (kvcb + c) * 8],
                  Vg + (krow0 + 64) * QS + (kvcb + c) * 8);
        }
        cpa_commit();

        // mask: 4096 ints -> bias floats (0 or -1e30), overlapped with cp.async
#pragma unroll
        for (int i = 0; i < 4; i++) {
            const int idx = t + 256 * i;   // int4 chunk id, 1024 total
            int4 m4 = ((const int4*)(mask + (size_t)b * S_LEN))[idx];
            float4 f4;
            f4.x = m4.x ? -1e30f : 0.f;
            f4.y = m4.y ? -1e30f : 0.f;
            f4.z = m4.z ? -1e30f : 0.f;
            f4.w = m4.w ? -1e30f : 0.f;
            ((float4*)biasf)[idx] = f4;
        }
    }

    unsigned qa[4][4];       // Q fragments (one m16 tile), loaded once at jb==0
    float o[8][4] = {};
    float ol[4] = {};        // l via ones-MMA (c0 = row g, c2 = row g+8)

    const int NT = S_LEN / 64;   // 64
#pragma unroll 3
    for (int jb = 0; jb < NT; jb++) {
        const int stage = jb % 3;
        if (jb + 1 < NT) cpa_wait1(); else cpa_wait0();
        __syncthreads();   // copies visible; all warps done with iter jb-1

        if (jb == 0) {
#pragma unroll
            for (int kc = 0; kc < 4; kc++)
                ldsm4(qa[kc], &Qh[(R0 + (q8 & 1) * 8 + ri) * HST
                                  + kc * 16 + (q8 >> 1) * 8]);
        }

        // prefetch stage jb+2 (its buffer was read at iter jb-1 — safe now)
        if (jb + 2 < NT) {
            const size_t krow = (size_t)b * S_LEN + (jb + 2) * 64 + kvrow;
            const int sbuf = (jb + 2) % 3;
#pragma unroll
            for (int c = 0; c < 2; c++) {
                cpa16(&Kh[sbuf * 64 * HST + kvrow * HST + (kvcb + c) * 8],
                      Kg + krow * QS + (kvcb + c) * 8);
                cpa16(&Vh[sbuf * 64 * HST + kvrow * HST + (kvcb + c) * 8],
                      Vg + krow * QS + (kvcb + c) * 8);
            }
            cpa_commit();
        }

        const __half* Kb = Kh + stage * 64 * HST;
        const __half* Vb = Vh + stage * 64 * HST;
        const float* brow = biasf + jb * 64;

        // ---- S = Q @ K^T (Q from registers) ----
        float s[8][4] = {};
#pragma unroll
        for (int kc = 0; kc < 4; kc++) {
#pragma unroll
            for (int nt = 0; nt < 8; nt += 2) {
                unsigned bb[4];
                ldsm4(bb, &Kb[((nt + (q8 >> 1)) * 8 + ri) * HST + kc * 16 + (q8 & 1) * 8]);
                mma_f16(s[nt],     qa[kc], bb[0], bb[1]);
                mma_f16(s[nt + 1], qa[kc], bb[2], bb[3]);
            }
        }

        // ---- p = ex2.f16x2(half2(s*CEXP + bias)) straight into PV A-frags ----
        unsigned pa[4][4];
#pragma unroll
        for (int nt = 0; nt < 8; nt++) {
            const float2 bj = *(const float2*)&brow[nt * 8 + 2 * tig];
            unsigned x01 = pack2(fmaf(s[nt][0], CEXP, bj.x),
                                 fmaf(s[nt][1], CEXP, bj.y));
            unsigned x23 = pack2(fmaf(s[nt][2], CEXP, bj.x),
                                 fmaf(s[nt][3], CEXP, bj.y));
            pa[nt >> 1][(nt & 1) * 2 + 0] = h2ex2(x01);
            pa[nt >> 1][(nt & 1) * 2 + 1] = h2ex2(x23);
        }

        // ---- O += P @ V (V via ldmatrix.trans); l += P @ ones ----
#pragma unroll
        for (int kc = 0; kc < 4; kc++) {
#pragma unroll
            for (int nt = 0; nt < 8; nt += 2) {
                unsigned bb[4];
                ldsm4t(bb, &Vb[(kc * 16 + (q8 & 1) * 8 + ri) * HST + (nt + (q8 >> 1)) * 8]);
                mma_f16(o[nt],     pa[kc], bb[0], bb[1]);
                mma_f16(o[nt + 1], pa[kc], bb[2], bb[3]);
            }
            mma_f16(ol, pa[kc], ONES2, ONES2);
        }
    }

    // ---- normalize + write (half out); ol[0] = l(row g), ol[2] = l(row g+8)
    {
        const float inv0 = 1.f / ol[0];
        const float inv1 = 1.f / ol[2];
        const int row0 = qrow0 + R0 + (lane >> 2);
#pragma unroll
        for (int nt = 0; nt < 8; nt++) {
            const int col = hcol + nt * 8 + 2 * tig;
            *(unsigned*)&Og[(size_t)row0 * D_MODEL + col] =
                pack2(o[nt][0] * inv0, o[nt][1] * inv0);
            *(unsigned*)&Og[(size_t)(row0 + 8) * D_MODEL + col] =
                pack2(o[nt][2] * inv1, o[nt][3] * inv1);
        }
    }
}

#define ATTN_SMEM ((128 * HST + 3 * 64 * HST + 3 * 64 * HST) * 2 + S_LEN * 4) // 90112

// ---------------------------------------------------------------------------
extern "C" void kernel_launch(void* const* d_in, const int* in_sizes, int n_in,
                              void* d_out, int out_size)
{
    const float* h   = (const float*)d_in[0];
    const float* Wq  = (const float*)d_in[1];
    const float* bq  = (const float*)d_in[2];
    const float* Wk  = (const float*)d_in[3];
    const float* bk  = (const float*)d_in[4];
    const float* Wv  = (const float*)d_in[5];
    const float* bv  = (const float*)d_in[6];
    const float* Wo  = (const float*)d_in[7];
    const float* bo  = (const float*)d_in[8];
    const int*   msk = (const int*)d_in[9];
    float* out = (float*)d_out;

    void *ph16, *pwqkv, *pbqkv, *pwo, *pqkv, *pa;
    cudaGetSymbolAddress(&ph16, g_h16);
    cudaGetSymbolAddress(&pwqkv, g_wqkv);
    cudaGetSymbolAddress(&pbqkv, g_bqkv);
    cudaGetSymbolAddress(&pwo, g_wo);
    cudaGetSymbolAddress(&pqkv, g_qkv);
    cudaGetSymbolAddress(&pa, g_att);

    // single fused fp32 -> fp16 pre-conversion
    {
        const int total = NH4 + 4 * NW4 + 3 * NB4;
        cvt_all<<<(total + 255) / 256, 256>>>(h, Wq, Wk, Wv, Wo, bq, bk, bv,
                                              (__half*)ph16, (__half*)pwqkv,
                                              (__half*)pwo, (float*)pbqkv);
    }

    cudaFuncSetAttribute(attn_tc, cudaFuncAttributeMaxDynamicSharedMemorySize,
                         ATTN_SMEM);
    cudaFuncSetAttribute(gemm_h<true>, cudaFuncAttributeMaxDynamicSharedMemorySize,
                         GEMM_SMEM);
    cudaFuncSetAttribute(gemm_h<false>, cudaFuncAttributeMaxDynamicSharedMemorySize,
                         GEMM_SMEM);

    // fused QKV projection: [8192 x 2304] = h @ [Wq|Wk|Wv]^T + b
    dim3 qgrid(QS / 128, ROWS / 128);       // (18, 64)
    gemm_h<true><<<qgrid, dim3(512), GEMM_SMEM>>>(
        (const __half*)ph16, (const __half*)pwqkv,
        (const float*)pbqkv, pqkv, ROWS, QS, D_MODEL);

    dim3 agrid(S_LEN / 128, BATCH * NH);    // (32, 24)
    attn_tc<<<agrid, dim3(256), ATTN_SMEM>>>((const __half*)pqkv, msk, (__half*)pa);

    dim3 ogrid(D_MODEL / 128, ROWS / 128);  // (6, 64)
    gemm_h<false><<<ogrid, dim3(512), GEMM_SMEM>>>(
        (const __half*)pa, (const __half*)pwo, bo, out,
        ROWS, D_MODEL, D_MODEL);
}